// round 3
// baseline (speedup 1.0000x reference)
#include <cuda_runtime.h>

#define B_ 256
#define T_ 512
#define D_ 128
#define H_ 128
#define G_ 384          // 3H, gate order z|r|h
#define BT_ (B_*T_)

__device__ float g_xp[(size_t)BT_ * G_];   // 201 MB scratch
__device__ float g_h0[(size_t)BT_ * H_];   // 67 MB scratch

typedef unsigned long long u64;

static __device__ __forceinline__ u64 pack2(float a, float b) {
    u64 r; asm("mov.b64 %0, {%1, %2};" : "=l"(r) : "f"(a), "f"(b)); return r;
}
static __device__ __forceinline__ void unpack2(u64 v, float &a, float &b) {
    asm("mov.b64 {%0, %1}, %2;" : "=f"(a), "=f"(b) : "l"(v));
}
static __device__ __forceinline__ u64 fma2(u64 a, u64 b, u64 c) {
    u64 d; asm("fma.rn.f32x2 %0, %1, %2, %3;" : "=l"(d) : "l"(a), "l"(b), "l"(c)); return d;
}
static __device__ __forceinline__ float sigf(float a) {
    return __fdividef(1.0f, 1.0f + __expf(-a));
}
static __device__ __forceinline__ float tanh_fast(float a) {
    return __fdividef(2.0f, 1.0f + __expf(-2.0f * a)) - 1.0f;
}

// ---------------------------------------------------------------------------
// Thread layout (both kernels): 384 threads, 12 warps. Within a warp:
//   kg = lane>>4 (k half: 0 -> k[0,64), 1 -> k[64,128)), kb = kg*64
//   jbase = warp*32 + (lane&15)*2  -> each thread owns 2 adjacent j columns
// W/U slice per thread: 32 k-pairs x 2 j = 64 f32x2 pairs (128 regs).
// k-reduction = one shfl.xor(16) + add (no smem partials).
// ---------------------------------------------------------------------------

// Projection: out[n,g] = sum_k x[n,k]*W[k,g] + bias[g]; 4 rows/iter, 1 bar/iter.
__global__ __launch_bounds__(384, 1)
void proj_kernel(const float* __restrict__ x, const float* __restrict__ W,
                 const float* __restrict__ bias, float* __restrict__ out,
                 int rows_per_block)
{
    __shared__ __align__(16) float x_sm[2][4][D_];
    const int tid   = threadIdx.x;
    const int lane  = tid & 31;
    const int warp  = tid >> 5;
    const int kb    = (lane >> 4) * 64;
    const int jbase = warp * 32 + (lane & 15) * 2;

    u64 w2[64];
#pragma unroll
    for (int i = 0; i < 32; i++) {
        w2[i]      = pack2(W[(kb + 2*i) * G_ + jbase],
                           W[(kb + 2*i + 1) * G_ + jbase]);
        w2[32 + i] = pack2(W[(kb + 2*i) * G_ + jbase + 1],
                           W[(kb + 2*i + 1) * G_ + jbase + 1]);
    }
    const float bj0 = bias[jbase], bj1 = bias[jbase + 1];

    const int row0 = blockIdx.x * rows_per_block;
    for (int i = tid; i < 4 * D_; i += 384) {
        int r = i >> 7, k = i & 127;
        x_sm[0][r][k] = x[(size_t)(row0 + r) * D_ + k];
    }
    __syncthreads();

    const int iters = rows_per_block / 4;
    for (int it = 0; it < iters; it++) {
        const int rbase = row0 + it * 4;
        if (it + 1 < iters) {
            for (int i = tid; i < 4 * D_; i += 384) {
                int r = i >> 7, k = i & 127;
                x_sm[(it + 1) & 1][r][k] = x[(size_t)(rbase + 4 + r) * D_ + k];
            }
        }
        const float* xs = &x_sm[it & 1][0][0];
#pragma unroll
        for (int r = 0; r < 4; r++) {
            u64 a0x = 0, a0y = 0, a1x = 0, a1y = 0;
#pragma unroll
            for (int i = 0; i < 16; i++) {
                ulonglong2 hv = *(const ulonglong2*)&xs[r * D_ + kb + 4*i];
                a0x = fma2(hv.x, w2[2*i],        a0x);
                a0y = fma2(hv.y, w2[2*i + 1],    a0y);
                a1x = fma2(hv.x, w2[32 + 2*i],   a1x);
                a1y = fma2(hv.y, w2[32 + 2*i+1], a1y);
            }
            float p, q, s, t2;
            unpack2(a0x, p, q); unpack2(a0y, s, t2);
            float v0 = (p + q) + (s + t2);
            unpack2(a1x, p, q); unpack2(a1y, s, t2);
            float v1 = (p + q) + (s + t2);
            v0 += __shfl_xor_sync(0xffffffffu, v0, 16);
            v1 += __shfl_xor_sync(0xffffffffu, v1, 16);
            if (lane < 16) {
                float2 o = make_float2(v0 + bj0, v1 + bj1);
                *(float2*)&out[(size_t)(rbase + r) * G_ + jbase] = o;
            }
        }
        __syncthreads();
    }
}

// ---------------------------------------------------------------------------
// GRU scan: block owns 2 rows. Skewed phases: phase p does FMA(row=p&1, t=p>>1)
// overlapped with the gate epilogue of the other row. 1 barrier per phase.
// ---------------------------------------------------------------------------
__global__ __launch_bounds__(384, 1)
void gru_scan(const float* __restrict__ U, const float* __restrict__ brec,
              const float* __restrict__ xp, float* __restrict__ out)
{
    __shared__ __align__(16) float h_sm[2][H_];
    __shared__ float rec_sm[2][G_];   // [row][j], bias pre-added
    __shared__ float xp_sm[2][G_];    // [row][j]
    const int tid   = threadIdx.x;
    const int lane  = tid & 31;
    const int warp  = tid >> 5;
    const int kb    = (lane >> 4) * 64;
    const int jbase = warp * 32 + (lane & 15) * 2;

    u64 u2[64];
#pragma unroll
    for (int i = 0; i < 32; i++) {
        u2[i]      = pack2(U[(kb + 2*i) * G_ + jbase],
                           U[(kb + 2*i + 1) * G_ + jbase]);
        u2[32 + i] = pack2(U[(kb + 2*i) * G_ + jbase + 1],
                           U[(kb + 2*i + 1) * G_ + jbase + 1]);
    }
    const float bj0 = brec[jbase], bj1 = brec[jbase + 1];

    if (tid < 2 * H_) h_sm[tid >> 7][tid & 127] = 0.0f;

    const int b0 = blockIdx.x * 2;
    const float* xrow[2] = { xp + (size_t)b0 * T_ * G_,
                             xp + (size_t)(b0 + 1) * T_ * G_ };
    float* orow[2] = { out + (size_t)b0 * T_ * H_,
                       out + (size_t)(b0 + 1) * T_ * H_ };
    float xpr[2] = { xrow[0][tid], xrow[1][tid] };   // xp[r][t=0]
    __syncthreads();

    for (int p = 0; p < 2 * T_ + 1; p++) {
        const int r  = p & 1;
        const int t  = p >> 1;
        const int er = r ^ 1;
        const int et = (p - 1) >> 1;
        const bool epi = (p > 0) && (tid < H_);

        // epilogue loads issued early (overlap with FMA below)
        float rz, rr_, rh, xz, xr_, xh, hp;
        if (epi) {
            rz  = rec_sm[er][tid];
            rr_ = rec_sm[er][tid + H_];
            rh  = rec_sm[er][tid + 2 * H_];
            xz  = xp_sm[er][tid];
            xr_ = xp_sm[er][tid + H_];
            xh  = xp_sm[er][tid + 2 * H_];
            hp  = h_sm[er][tid];
        }

        if (t < T_) {
            // publish xp for this (r,t); prefetch next step's into register
            xp_sm[r][tid] = xpr[r];
            if (t + 1 < T_) xpr[r] = xrow[r][(size_t)(t + 1) * G_ + tid];

            u64 a0x = 0, a0y = 0, a1x = 0, a1y = 0;
#pragma unroll
            for (int i = 0; i < 16; i++) {
                ulonglong2 hv = *(const ulonglong2*)&h_sm[r][kb + 4*i];
                a0x = fma2(hv.x, u2[2*i],          a0x);
                a0y = fma2(hv.y, u2[2*i + 1],      a0y);
                a1x = fma2(hv.x, u2[32 + 2*i],     a1x);
                a1y = fma2(hv.y, u2[32 + 2*i + 1], a1y);
            }
            float pa, pb, pc, pd;
            unpack2(a0x, pa, pb); unpack2(a0y, pc, pd);
            float v0 = (pa + pb) + (pc + pd);
            unpack2(a1x, pa, pb); unpack2(a1y, pc, pd);
            float v1 = (pa + pb) + (pc + pd);
            v0 += __shfl_xor_sync(0xffffffffu, v0, 16);
            v1 += __shfl_xor_sync(0xffffffffu, v1, 16);
            if (lane < 16)
                *(float2*)&rec_sm[r][jbase] = make_float2(v0 + bj0, v1 + bj1);
        }

        if (epi) {
            float z  = sigf(xz + rz);
            float rg = sigf(xr_ + rr_);
            float hh = tanh_fast(xh + rg * rh);
            float hn = hh + z * (hp - hh);
            h_sm[er][tid] = hn;
            orow[er][(size_t)et * H_ + tid] = hn;
        }
        __syncthreads();
    }
}

// ---------------------------------------------------------------------------
extern "C" void kernel_launch(void* const* d_in, const int* in_sizes, int n_in,
                              void* d_out, int out_size)
{
    const float* x  = (const float*)d_in[0];
    const float* W0 = (const float*)d_in[1];
    const float* U0 = (const float*)d_in[2];
    const float* b0 = (const float*)d_in[3];
    const float* W1 = (const float*)d_in[4];
    const float* U1 = (const float*)d_in[5];
    const float* b1 = (const float*)d_in[6];
    float* out = (float*)d_out;

    float *xp, *h0;
    cudaGetSymbolAddress((void**)&xp, g_xp);
    cudaGetSymbolAddress((void**)&h0, g_h0);

    const int PROJ_GRID = 1024;
    const int rpb = BT_ / PROJ_GRID;   // 128 rows per block

    // layer 0
    proj_kernel<<<PROJ_GRID, 384>>>(x, W0, b0 /*b_in*/, xp, rpb);
    gru_scan<<<B_ / 2, 384>>>(U0, b0 + G_ /*b_rec*/, xp, h0);
    // layer 1
    proj_kernel<<<PROJ_GRID, 384>>>(h0, W1, b1, xp, rpb);
    gru_scan<<<B_ / 2, 384>>>(U1, b1 + G_, xp, out);
}

// round 4
// speedup vs baseline: 1.4522x; 1.4522x over previous
#include <cuda_runtime.h>

#define B_ 256
#define T_ 512
#define D_ 128
#define H_ 128
#define G_ 384          // 3H, gate order z|r|h
#define BT_ (B_*T_)

__device__ float g_xp[(size_t)BT_ * G_];   // 201 MB scratch
__device__ float g_h0[(size_t)BT_ * H_];   // 67 MB scratch

typedef unsigned long long u64;

static __device__ __forceinline__ u64 pack2(float a, float b) {
    u64 r; asm("mov.b64 %0, {%1, %2};" : "=l"(r) : "f"(a), "f"(b)); return r;
}
static __device__ __forceinline__ void unpack2(u64 v, float &a, float &b) {
    asm("mov.b64 {%0, %1}, %2;" : "=f"(a), "=f"(b) : "l"(v));
}
static __device__ __forceinline__ u64 fma2(u64 a, u64 b, u64 c) {
    u64 d; asm("fma.rn.f32x2 %0, %1, %2, %3;" : "=l"(d) : "l"(a), "l"(b), "l"(c)); return d;
}
static __device__ __forceinline__ float sigf(float a) {
    return __fdividef(1.0f, 1.0f + __expf(-a));
}
static __device__ __forceinline__ float tanh_fast(float a) {
    return __fdividef(2.0f, 1.0f + __expf(-2.0f * a)) - 1.0f;
}

// ---------------------------------------------------------------------------
// Layout (both kernels): 384 threads; thread tid owns output column j = tid
// with the FULL k=128 dot product in registers (64 f32x2 pairs, packed along
// k). No cross-thread reduction: one complete rec[j]/out[j] per thread.
// Shared h/x reads are pure warp-broadcast LDS.128.
// ---------------------------------------------------------------------------

// Projection: out[n,g] = sum_k x[n,k]*W[k,g] + bias[g]; 8 rows/iter, 1 bar/iter.
__global__ __launch_bounds__(384, 1)
void proj_kernel(const float* __restrict__ x, const float* __restrict__ W,
                 const float* __restrict__ bias, float* __restrict__ out,
                 int rows_per_block)
{
    __shared__ __align__(16) float x_sm[2][8][D_];
    const int tid = threadIdx.x;

    u64 w2[64];
#pragma unroll
    for (int i = 0; i < 64; i++)
        w2[i] = pack2(W[(2*i) * G_ + tid], W[(2*i + 1) * G_ + tid]);
    const float bj = bias[tid];

    const int row0 = blockIdx.x * rows_per_block;
    if (tid < 256)
        ((float4*)&x_sm[0][0][0])[tid] =
            ((const float4*)(x + (size_t)row0 * D_))[tid];
    __syncthreads();

    const int iters = rows_per_block / 8;
    int buf = 0;
    for (int it = 0; it < iters; it++) {
        const int rbase = row0 + it * 8;
        float4 nx;
        const bool pre = (it + 1 < iters) && (tid < 256);
        if (pre)
            nx = ((const float4*)(x + (size_t)(rbase + 8) * D_))[tid];

#pragma unroll
        for (int r = 0; r < 8; r++) {
            u64 pacc = 0, qacc = 0;
            const float* xs = &x_sm[buf][r][0];
#pragma unroll
            for (int i = 0; i < 32; i++) {
                ulonglong2 hv = *(const ulonglong2*)&xs[4*i];
                pacc = fma2(hv.x, w2[2*i],     pacc);
                qacc = fma2(hv.y, w2[2*i + 1], qacc);
            }
            float a, b, c, d;
            unpack2(pacc, a, b); unpack2(qacc, c, d);
            out[(size_t)(rbase + r) * G_ + tid] = ((a + b) + (c + d)) + bj;
        }
        if (pre)
            ((float4*)&x_sm[buf ^ 1][0][0])[tid] = nx;
        __syncthreads();
        buf ^= 1;
    }
}

// ---------------------------------------------------------------------------
// GRU scan: block owns 2 batch rows for all T steps. Per step: all 384
// threads compute rec[j] for both rows (no reduction), one barrier, then
// tid<256 run the fast-math gate epilogue (xp held in registers, prefetched
// during the FMA phase), one barrier.
// ---------------------------------------------------------------------------
__global__ __launch_bounds__(384, 1)
void gru_scan(const float* __restrict__ U, const float* __restrict__ brec,
              const float* __restrict__ xp, float* __restrict__ out)
{
    __shared__ __align__(16) float h_sm[2][H_];
    __shared__ float rec_sm[2][G_];   // bias pre-added
    const int tid = threadIdx.x;

    u64 u2[64];
#pragma unroll
    for (int i = 0; i < 64; i++)
        u2[i] = pack2(U[(2*i) * G_ + tid], U[(2*i + 1) * G_ + tid]);
    const float bj = brec[tid];

    if (tid < 256) h_sm[tid >> 7][tid & 127] = 0.0f;

    const int b0 = blockIdx.x * 2;
    // epilogue role (tid < 256): row erow, unit eu
    const int erow = tid >> 7, eu = tid & 127;
    const float* exr = xp + (size_t)(b0 + erow) * T_ * G_;
    float* eo = out + (size_t)(b0 + erow) * T_ * H_;
    float xz = 0.f, xr_ = 0.f, xh = 0.f;
    if (tid < 256) {
        xz  = exr[eu];
        xr_ = exr[eu + H_];
        xh  = exr[eu + 2 * H_];
    }
    __syncthreads();

    for (int t = 0; t < T_; t++) {
        // --- matvec for both rows, full column per thread ---
        u64 p0 = 0, q0 = 0, p1 = 0, q1 = 0;
#pragma unroll
        for (int i = 0; i < 32; i++) {
            ulonglong2 h0v = *(const ulonglong2*)&h_sm[0][4*i];
            ulonglong2 h1v = *(const ulonglong2*)&h_sm[1][4*i];
            p0 = fma2(h0v.x, u2[2*i],     p0);
            q0 = fma2(h0v.y, u2[2*i + 1], q0);
            p1 = fma2(h1v.x, u2[2*i],     p1);
            q1 = fma2(h1v.y, u2[2*i + 1], q1);
        }
        float a, b, c, d;
        unpack2(p0, a, b); unpack2(q0, c, d);
        rec_sm[0][tid] = ((a + b) + (c + d)) + bj;
        unpack2(p1, a, b); unpack2(q1, c, d);
        rec_sm[1][tid] = ((a + b) + (c + d)) + bj;

        // prefetch next step's xp into registers (latency hidden by FMA above)
        float nxz = 0.f, nxr = 0.f, nxh = 0.f;
        if (tid < 256 && t + 1 < T_) {
            const float* xn = exr + (size_t)(t + 1) * G_;
            nxz = xn[eu];
            nxr = xn[eu + H_];
            nxh = xn[eu + 2 * H_];
        }
        __syncthreads();

        // --- gate epilogue ---
        if (tid < 256) {
            float rz = rec_sm[erow][eu];
            float rr = rec_sm[erow][eu + H_];
            float rh = rec_sm[erow][eu + 2 * H_];
            float z  = sigf(xz + rz);
            float rg = sigf(xr_ + rr);
            float hh = tanh_fast(xh + rg * rh);
            float hp = h_sm[erow][eu];
            float hn = hh + z * (hp - hh);
            h_sm[erow][eu] = hn;
            eo[(size_t)t * H_ + eu] = hn;
            xz = nxz; xr_ = nxr; xh = nxh;
        }
        __syncthreads();
    }
}

// ---------------------------------------------------------------------------
extern "C" void kernel_launch(void* const* d_in, const int* in_sizes, int n_in,
                              void* d_out, int out_size)
{
    const float* x  = (const float*)d_in[0];
    const float* W0 = (const float*)d_in[1];
    const float* U0 = (const float*)d_in[2];
    const float* b0 = (const float*)d_in[3];
    const float* W1 = (const float*)d_in[4];
    const float* U1 = (const float*)d_in[5];
    const float* b1 = (const float*)d_in[6];
    float* out = (float*)d_out;

    float *xp, *h0;
    cudaGetSymbolAddress((void**)&xp, g_xp);
    cudaGetSymbolAddress((void**)&h0, g_h0);

    const int PROJ_GRID = 1024;
    const int rpb = BT_ / PROJ_GRID;   // 128 rows per block

    // layer 0
    proj_kernel<<<PROJ_GRID, 384>>>(x, W0, b0 /*b_in*/, xp, rpb);
    gru_scan<<<B_ / 2, 384>>>(U0, b0 + G_ /*b_rec*/, xp, h0);
    // layer 1
    proj_kernel<<<PROJ_GRID, 384>>>(h0, W1, b1, xp, rpb);
    gru_scan<<<B_ / 2, 384>>>(U1, b1 + G_, xp, out);
}

// round 5
// speedup vs baseline: 1.5485x; 1.0663x over previous
#include <cuda_runtime.h>

#define B_ 256
#define T_ 512
#define D_ 128
#define H_ 128
#define G_ 384          // 3H, gate order z|r|h
#define BT_ (B_*T_)

__device__ float g_xp[(size_t)BT_ * G_];   // 201 MB scratch
__device__ float g_h0[(size_t)BT_ * H_];   // 67 MB scratch

typedef unsigned long long u64;

static __device__ __forceinline__ u64 pack2(float a, float b) {
    u64 r; asm("mov.b64 %0, {%1, %2};" : "=l"(r) : "f"(a), "f"(b)); return r;
}
static __device__ __forceinline__ void unpack2(u64 v, float &a, float &b) {
    asm("mov.b64 {%0, %1}, %2;" : "=f"(a), "=f"(b) : "l"(v));
}
static __device__ __forceinline__ u64 fma2(u64 a, u64 b, u64 c) {
    u64 d; asm("fma.rn.f32x2 %0, %1, %2, %3;" : "=l"(d) : "l"(a), "l"(b), "l"(c)); return d;
}
static __device__ __forceinline__ float sigf(float a) {
    return __fdividef(1.0f, 1.0f + __expf(-a));            // MUFU path
}
static __device__ __forceinline__ float tanh_fast(float a) {
    return __fdividef(2.0f, 1.0f + __expf(-2.0f * a)) - 1.0f;
}

// ---------------------------------------------------------------------------
// Layout (both kernels): 384 threads = 4 k-groups (kg, 32 k each; warp-uniform
// since 96 = 3 warps) x 96 j-groups x 4 cols. Thread holds W/U[32k x 4j] as
// 64 f32x2 pairs (128 regs). Per row: 8 broadcast LDS.128 -> 64 FFMA2
// (1:8 LDS:FMA). k-reduction via smem partials (shfl measured slower).
// ---------------------------------------------------------------------------

// Projection: out[n,g] = sum_k x[n,k]*W[k,g] + bias[g]; 4 rows/iter.
__global__ __launch_bounds__(384, 1)
void proj_kernel(const float* __restrict__ x, const float* __restrict__ W,
                 const float* __restrict__ bias, float* __restrict__ out,
                 int rows_per_block)
{
    __shared__ __align__(16) float x_sm[2][4][D_];
    __shared__ __align__(16) float part[4][4][G_];   // [row][kg][j]  24 KB
    const int tid = threadIdx.x;
    const int kg  = tid / 96;
    const int jg  = tid - kg * 96;
    const int j0  = jg * 4;
    const int kb  = kg * 32;

    u64 w2[16][4];
#pragma unroll
    for (int i = 0; i < 16; i++)
#pragma unroll
        for (int jj = 0; jj < 4; jj++)
            w2[i][jj] = pack2(W[(kb + 2*i) * G_ + j0 + jj],
                              W[(kb + 2*i + 1) * G_ + j0 + jj]);
    const float bj = bias[tid];          // epilogue: this thread owns column tid

    const int row0 = blockIdx.x * rows_per_block;
    if (tid < 128)
        ((float4*)&x_sm[0][0][0])[tid] =
            ((const float4*)(x + (size_t)row0 * D_))[tid];
    __syncthreads();

    const int iters = rows_per_block / 4;
    int buf = 0;
    for (int it = 0; it < iters; it++) {
        const int rbase = row0 + it * 4;
        float4 nx;
        const bool pre = (it + 1 < iters) && (tid < 128);
        if (pre)
            nx = ((const float4*)(x + (size_t)(rbase + 4) * D_))[tid];

#pragma unroll
        for (int r = 0; r < 4; r++) {
            u64 acc0 = 0, acc1 = 0, acc2 = 0, acc3 = 0;
            const float* xs = &x_sm[buf][r][kb];
#pragma unroll
            for (int i2 = 0; i2 < 8; i2++) {
                ulonglong2 hv = *(const ulonglong2*)&xs[4*i2];
                acc0 = fma2(hv.x, w2[2*i2][0],     acc0);
                acc0 = fma2(hv.y, w2[2*i2 + 1][0], acc0);
                acc1 = fma2(hv.x, w2[2*i2][1],     acc1);
                acc1 = fma2(hv.y, w2[2*i2 + 1][1], acc1);
                acc2 = fma2(hv.x, w2[2*i2][2],     acc2);
                acc2 = fma2(hv.y, w2[2*i2 + 1][2], acc2);
                acc3 = fma2(hv.x, w2[2*i2][3],     acc3);
                acc3 = fma2(hv.y, w2[2*i2 + 1][3], acc3);
            }
            float4 p; float a, b;
            unpack2(acc0, a, b); p.x = a + b;
            unpack2(acc1, a, b); p.y = a + b;
            unpack2(acc2, a, b); p.z = a + b;
            unpack2(acc3, a, b); p.w = a + b;
            *(float4*)&part[r][kg][j0] = p;
        }
        if (pre)
            ((float4*)&x_sm[buf ^ 1][0][0])[tid] = nx;
        __syncthreads();
#pragma unroll
        for (int r = 0; r < 4; r++) {
            float s = part[r][0][tid] + part[r][1][tid]
                    + part[r][2][tid] + part[r][3][tid] + bj;
            out[(size_t)(rbase + r) * G_ + tid] = s;
        }
        __syncthreads();
        buf ^= 1;
    }
}

// ---------------------------------------------------------------------------
// GRU scan: block owns 2 batch rows for all T steps. Per step: matvec ->
// partials -> bar -> 256-thread fast-math gate epilogue (xp in registers,
// prefetched during the FMA phase) -> bar.
// ---------------------------------------------------------------------------
__global__ __launch_bounds__(384, 1)
void gru_scan(const float* __restrict__ U, const float* __restrict__ brec,
              const float* __restrict__ xp, float* __restrict__ out)
{
    __shared__ __align__(16) float h_sm[2][H_];
    __shared__ __align__(16) float part[2][4][G_];   // [row][kg][j]
    const int tid = threadIdx.x;
    const int kg  = tid / 96;
    const int jg  = tid - kg * 96;
    const int j0  = jg * 4;
    const int kb  = kg * 32;

    u64 u2[16][4];
#pragma unroll
    for (int i = 0; i < 16; i++)
#pragma unroll
        for (int jj = 0; jj < 4; jj++)
            u2[i][jj] = pack2(U[(kb + 2*i) * G_ + j0 + jj],
                              U[(kb + 2*i + 1) * G_ + j0 + jj]);

    if (tid < 256) h_sm[tid >> 7][tid & 127] = 0.0f;

    const int b0 = blockIdx.x * 2;
    // epilogue role (tid < 256): row erow, unit eu
    const int erow = tid >> 7, eu = tid & 127;
    const float* exr = xp + (size_t)(b0 + erow) * T_ * G_;
    float* eo = out + (size_t)(b0 + erow) * T_ * H_;
    float bz = 0.f, brr = 0.f, bh = 0.f;
    float xz = 0.f, xr_ = 0.f, xh = 0.f;
    if (tid < 256) {
        bz  = brec[eu];
        brr = brec[eu + H_];
        bh  = brec[eu + 2 * H_];
        xz  = exr[eu];
        xr_ = exr[eu + H_];
        xh  = exr[eu + 2 * H_];
    }
    __syncthreads();

    for (int t = 0; t < T_; t++) {
        // --- matvec: both rows, 4 j-cols x 32 k per thread ---
#pragma unroll
        for (int r = 0; r < 2; r++) {
            u64 acc0 = 0, acc1 = 0, acc2 = 0, acc3 = 0;
            const float* hs = &h_sm[r][kb];
#pragma unroll
            for (int i2 = 0; i2 < 8; i2++) {
                ulonglong2 hv = *(const ulonglong2*)&hs[4*i2];
                acc0 = fma2(hv.x, u2[2*i2][0],     acc0);
                acc0 = fma2(hv.y, u2[2*i2 + 1][0], acc0);
                acc1 = fma2(hv.x, u2[2*i2][1],     acc1);
                acc1 = fma2(hv.y, u2[2*i2 + 1][1], acc1);
                acc2 = fma2(hv.x, u2[2*i2][2],     acc2);
                acc2 = fma2(hv.y, u2[2*i2 + 1][2], acc2);
                acc3 = fma2(hv.x, u2[2*i2][3],     acc3);
                acc3 = fma2(hv.y, u2[2*i2 + 1][3], acc3);
            }
            float4 p; float a, b;
            unpack2(acc0, a, b); p.x = a + b;
            unpack2(acc1, a, b); p.y = a + b;
            unpack2(acc2, a, b); p.z = a + b;
            unpack2(acc3, a, b); p.w = a + b;
            *(float4*)&part[r][kg][j0] = p;
        }

        // prefetch next step's xp into registers (hidden behind FMA/barrier)
        float nxz = 0.f, nxr = 0.f, nxh = 0.f;
        if (tid < 256 && t + 1 < T_) {
            const float* xn = exr + (size_t)(t + 1) * G_;
            nxz = xn[eu];
            nxr = xn[eu + H_];
            nxh = xn[eu + 2 * H_];
        }
        __syncthreads();

        // --- gate epilogue (fast math) ---
        if (tid < 256) {
            float rz = part[erow][0][eu] + part[erow][1][eu]
                     + part[erow][2][eu] + part[erow][3][eu] + bz;
            float rr = part[erow][0][eu+H_] + part[erow][1][eu+H_]
                     + part[erow][2][eu+H_] + part[erow][3][eu+H_] + brr;
            float rh = part[erow][0][eu+2*H_] + part[erow][1][eu+2*H_]
                     + part[erow][2][eu+2*H_] + part[erow][3][eu+2*H_] + bh;
            float z  = sigf(xz + rz);
            float rg = sigf(xr_ + rr);
            float hh = tanh_fast(xh + rg * rh);
            float hp = h_sm[erow][eu];
            float hn = hh + z * (hp - hh);
            h_sm[erow][eu] = hn;
            eo[(size_t)t * H_ + eu] = hn;
            xz = nxz; xr_ = nxr; xh = nxh;
        }
        __syncthreads();
    }
}

// ---------------------------------------------------------------------------
extern "C" void kernel_launch(void* const* d_in, const int* in_sizes, int n_in,
                              void* d_out, int out_size)
{
    const float* x  = (const float*)d_in[0];
    const float* W0 = (const float*)d_in[1];
    const float* U0 = (const float*)d_in[2];
    const float* b0 = (const float*)d_in[3];
    const float* W1 = (const float*)d_in[4];
    const float* U1 = (const float*)d_in[5];
    const float* b1 = (const float*)d_in[6];
    float* out = (float*)d_out;

    float *xp, *h0;
    cudaGetSymbolAddress((void**)&xp, g_xp);
    cudaGetSymbolAddress((void**)&h0, g_h0);

    const int PROJ_GRID = 1024;
    const int rpb = BT_ / PROJ_GRID;   // 128 rows per block

    // layer 0
    proj_kernel<<<PROJ_GRID, 384>>>(x, W0, b0 /*b_in*/, xp, rpb);
    gru_scan<<<B_ / 2, 384>>>(U0, b0 + G_ /*b_rec*/, xp, h0);
    // layer 1
    proj_kernel<<<PROJ_GRID, 384>>>(h0, W1, b1, xp, rpb);
    gru_scan<<<B_ / 2, 384>>>(U1, b1 + G_, xp, out);
}

// round 6
// speedup vs baseline: 1.7219x; 1.1120x over previous
#include <cuda_runtime.h>

#define B_ 256
#define T_ 512
#define D_ 128
#define H_ 128
#define G_ 384          // 3H, gate order z|r|h
#define BT_ (B_*T_)

__device__ float g_xp[(size_t)BT_ * G_];   // 201 MB scratch
__device__ float g_h0[(size_t)BT_ * H_];   // 67 MB scratch

typedef unsigned long long u64;

static __device__ __forceinline__ u64 pack2(float a, float b) {
    u64 r; asm("mov.b64 %0, {%1, %2};" : "=l"(r) : "f"(a), "f"(b)); return r;
}
static __device__ __forceinline__ void unpack2(u64 v, float &a, float &b) {
    asm("mov.b64 {%0, %1}, %2;" : "=f"(a), "=f"(b) : "l"(v));
}
static __device__ __forceinline__ u64 fma2(u64 a, u64 b, u64 c) {
    u64 d; asm("fma.rn.f32x2 %0, %1, %2, %3;" : "=l"(d) : "l"(a), "l"(b), "l"(c)); return d;
}
static __device__ __forceinline__ float sigf(float a) {
    return __fdividef(1.0f, 1.0f + __expf(-a));
}
static __device__ __forceinline__ float tanh_fast(float a) {
    return __fdividef(2.0f, 1.0f + __expf(-2.0f * a)) - 1.0f;
}

// ---------------------------------------------------------------------------
// Projection (R5 structure, 8 rows/iter): 384 threads = 4 kg x 96 jg x 4 cols.
// ---------------------------------------------------------------------------
#define PR_ 8
__global__ __launch_bounds__(384, 1)
void proj_kernel(const float* __restrict__ x, const float* __restrict__ W,
                 const float* __restrict__ bias, float* __restrict__ out,
                 int rows_per_block)
{
    __shared__ __align__(16) float x_sm[2][PR_][D_];
    __shared__ __align__(16) float part[PR_][4][G_];   // 48 KB
    const int tid = threadIdx.x;
    const int kg  = tid / 96;
    const int jg  = tid - kg * 96;
    const int j0  = jg * 4;
    const int kb  = kg * 32;

    u64 w2[16][4];
#pragma unroll
    for (int i = 0; i < 16; i++)
#pragma unroll
        for (int jj = 0; jj < 4; jj++)
            w2[i][jj] = pack2(W[(kb + 2*i) * G_ + j0 + jj],
                              W[(kb + 2*i + 1) * G_ + j0 + jj]);
    const float bj = bias[tid];

    const int row0 = blockIdx.x * rows_per_block;
    if (tid < PR_ * D_ / 4)
        ((float4*)&x_sm[0][0][0])[tid] =
            ((const float4*)(x + (size_t)row0 * D_))[tid];
    __syncthreads();

    const int iters = rows_per_block / PR_;
    int buf = 0;
    for (int it = 0; it < iters; it++) {
        const int rbase = row0 + it * PR_;
        float4 nx;
        const bool pre = (it + 1 < iters) && (tid < PR_ * D_ / 4);
        if (pre)
            nx = ((const float4*)(x + (size_t)(rbase + PR_) * D_))[tid];

#pragma unroll
        for (int r = 0; r < PR_; r++) {
            u64 acc0 = 0, acc1 = 0, acc2 = 0, acc3 = 0;
            const float* xs = &x_sm[buf][r][kb];
#pragma unroll
            for (int i2 = 0; i2 < 8; i2++) {
                ulonglong2 hv = *(const ulonglong2*)&xs[4*i2];
                acc0 = fma2(hv.x, w2[2*i2][0],     acc0);
                acc0 = fma2(hv.y, w2[2*i2 + 1][0], acc0);
                acc1 = fma2(hv.x, w2[2*i2][1],     acc1);
                acc1 = fma2(hv.y, w2[2*i2 + 1][1], acc1);
                acc2 = fma2(hv.x, w2[2*i2][2],     acc2);
                acc2 = fma2(hv.y, w2[2*i2 + 1][2], acc2);
                acc3 = fma2(hv.x, w2[2*i2][3],     acc3);
                acc3 = fma2(hv.y, w2[2*i2 + 1][3], acc3);
            }
            float4 p; float a, b;
            unpack2(acc0, a, b); p.x = a + b;
            unpack2(acc1, a, b); p.y = a + b;
            unpack2(acc2, a, b); p.z = a + b;
            unpack2(acc3, a, b); p.w = a + b;
            *(float4*)&part[r][kg][j0] = p;
        }
        if (pre)
            ((float4*)&x_sm[buf ^ 1][0][0])[tid] = nx;
        __syncthreads();
#pragma unroll
        for (int r = 0; r < PR_; r++) {
            float s = part[r][0][tid] + part[r][1][tid]
                    + part[r][2][tid] + part[r][3][tid] + bj;
            out[(size_t)(rbase + r) * G_ + tid] = s;
        }
        __syncthreads();
        buf ^= 1;
    }
}

// ---------------------------------------------------------------------------
// GRU scan: 256 threads, block owns 2 rows. Thread (u,kg): u = warp*16+lane&15,
// kg = lane>>4 (k-half). Owns gate-triple columns {u, u+128, u+256} over its
// k-half for BOTH rows; k-reduction = 3 shfl.xor(16); thread then runs the
// gate chain for row = kg. h double-buffered -> ONE barrier per step.
// ---------------------------------------------------------------------------
__global__ __launch_bounds__(256, 1)
void gru_scan(const float* __restrict__ U, const float* __restrict__ brec,
              const float* __restrict__ xp, float* __restrict__ out)
{
    // [buf][row][kg][68]: 68-float pitch puts the two kg slices 4 banks apart
    __shared__ __align__(16) float h_sm[2][2][2][68];
    const int tid  = threadIdx.x;
    const int lane = tid & 31;
    const int kg   = lane >> 4;            // 0/1 within warp
    const int u    = (tid >> 5) * 16 + (lane & 15);   // 0..127
    const int kb   = kg * 64;

    u64 w[3][32];
#pragma unroll
    for (int i = 0; i < 32; i++)
#pragma unroll
        for (int c = 0; c < 3; c++)
            w[c][i] = pack2(U[(kb + 2*i) * G_ + u + c*128],
                            U[(kb + 2*i + 1) * G_ + u + c*128]);
    const float bz = brec[u], br_ = brec[u + 128], bh = brec[u + 256];

    const int row = kg;                    // this thread's epilogue row
    const int b0  = blockIdx.x * 2;
    const float* exr = xp + (size_t)(b0 + row) * T_ * G_;
    float* eo = out + (size_t)(b0 + row) * T_ * H_;

    float xz  = exr[u];
    float xr_ = exr[u + 128];
    float xh  = exr[u + 256];
    float hp  = 0.0f;

    if (tid < 128) {
        h_sm[0][0][tid >> 6][tid & 63] = 0.0f;
        h_sm[0][1][tid >> 6][tid & 63] = 0.0f;
    }
    __syncthreads();

    for (int t = 0; t < T_; t++) {
        const int buf = t & 1;
        // prefetch next step's xp right away (≥ FMA-phase ahead of use)
        float nxz = 0.f, nxr = 0.f, nxh = 0.f;
        if (t + 1 < T_) {
            const float* xn = exr + (size_t)(t + 1) * G_;
            nxz = xn[u]; nxr = xn[u + 128]; nxh = xn[u + 256];
        }

        // --- matvec: both rows, 3 gate-cols, own k-half ---
        u64 a00 = 0, a01 = 0, a02 = 0, a10 = 0, a11 = 0, a12 = 0;
        const float* h0p = &h_sm[buf][0][kg][0];
        const float* h1p = &h_sm[buf][1][kg][0];
#pragma unroll
        for (int i2 = 0; i2 < 16; i2++) {
            ulonglong2 h0 = *(const ulonglong2*)&h0p[4*i2];
            ulonglong2 h1 = *(const ulonglong2*)&h1p[4*i2];
            a00 = fma2(h0.x, w[0][2*i2],     a00);
            a00 = fma2(h0.y, w[0][2*i2 + 1], a00);
            a01 = fma2(h0.x, w[1][2*i2],     a01);
            a01 = fma2(h0.y, w[1][2*i2 + 1], a01);
            a02 = fma2(h0.x, w[2][2*i2],     a02);
            a02 = fma2(h0.y, w[2][2*i2 + 1], a02);
            a10 = fma2(h1.x, w[0][2*i2],     a10);
            a10 = fma2(h1.y, w[0][2*i2 + 1], a10);
            a11 = fma2(h1.x, w[1][2*i2],     a11);
            a11 = fma2(h1.y, w[1][2*i2 + 1], a11);
            a12 = fma2(h1.x, w[2][2*i2],     a12);
            a12 = fma2(h1.y, w[2][2*i2 + 1], a12);
        }
        float s[2][3];
        { float a, b;
          unpack2(a00, a, b); s[0][0] = a + b;
          unpack2(a01, a, b); s[0][1] = a + b;
          unpack2(a02, a, b); s[0][2] = a + b;
          unpack2(a10, a, b); s[1][0] = a + b;
          unpack2(a11, a, b); s[1][1] = a + b;
          unpack2(a12, a, b); s[1][2] = a + b; }

        // k-reduction across kg (lane bit 4): I keep my row's partial, send
        // the other row's partial; partner sends mine back.
        float own0 = kg ? s[1][0] : s[0][0];
        float own1 = kg ? s[1][1] : s[0][1];
        float own2 = kg ? s[1][2] : s[0][2];
        float oth0 = kg ? s[0][0] : s[1][0];
        float oth1 = kg ? s[0][1] : s[1][1];
        float oth2 = kg ? s[0][2] : s[1][2];
        float rz = own0 + __shfl_xor_sync(0xffffffffu, oth0, 16) + bz;
        float rr = own1 + __shfl_xor_sync(0xffffffffu, oth1, 16) + br_;
        float rh = own2 + __shfl_xor_sync(0xffffffffu, oth2, 16) + bh;

        // --- gate chain for row = kg ---
        float z  = sigf(xz + rz);
        float rg = sigf(xr_ + rr);
        float hh = tanh_fast(xh + rg * rh);
        float hn = hh + z * (hp - hh);
        hp = hn;
        h_sm[buf ^ 1][row][u >> 6][u & 63] = hn;
        eo[(size_t)t * H_ + u] = hn;
        xz = nxz; xr_ = nxr; xh = nxh;
        __syncthreads();
    }
}

// ---------------------------------------------------------------------------
extern "C" void kernel_launch(void* const* d_in, const int* in_sizes, int n_in,
                              void* d_out, int out_size)
{
    const float* x  = (const float*)d_in[0];
    const float* W0 = (const float*)d_in[1];
    const float* U0 = (const float*)d_in[2];
    const float* b0 = (const float*)d_in[3];
    const float* W1 = (const float*)d_in[4];
    const float* U1 = (const float*)d_in[5];
    const float* b1 = (const float*)d_in[6];
    float* out = (float*)d_out;

    float *xp, *h0;
    cudaGetSymbolAddress((void**)&xp, g_xp);
    cudaGetSymbolAddress((void**)&h0, g_h0);

    const int PROJ_GRID = 1024;
    const int rpb = BT_ / PROJ_GRID;   // 128 rows per block

    // layer 0
    proj_kernel<<<PROJ_GRID, 384>>>(x, W0, b0 /*b_in*/, xp, rpb);
    gru_scan<<<B_ / 2, 256>>>(U0, b0 + G_ /*b_rec*/, xp, h0);
    // layer 1
    proj_kernel<<<PROJ_GRID, 384>>>(h0, W1, b1, xp, rpb);
    gru_scan<<<B_ / 2, 256>>>(U1, b1 + G_, xp, out);
}